// round 13
// baseline (speedup 1.0000x reference)
#include <cuda_runtime.h>
#include <cuda_bf16.h>

#define MAXM   512       // absolute per-class capacity (fallback path)
#define MAXB   256       // fast-path capacity (bitmap rows); actual m ~51
#define NCLS   80
#define TPB    256

__global__ void __launch_bounds__(TPB) k_fused(const float* __restrict__ boxes,
                                               const float* __restrict__ scores,
                                               const int*   __restrict__ cls,
                                               const float* __restrict__ loc,
                                               const float* __restrict__ deltas,
                                               const int*   __restrict__ stridep,
                                               float* __restrict__ out,
                                               int N, int L) {
    const int tid = threadIdx.x;

    if (blockIdx.x >= NCLS) {
        // ---------------- pred decode + centerness ----------------
        int i = (blockIdx.x - NCLS) * TPB + tid;
        if (i >= L) return;
        float s = (float)stridep[0];
        float4 d = ((const float4*)deltas)[i];
        float2 p = ((const float2*)loc)[i];
        float* o = out + N + 5 * i;
        o[0] = p.x - fmaxf(d.x, 0.0f) * s;
        o[1] = p.y - fmaxf(d.y, 0.0f) * s;
        o[2] = p.x + fmaxf(d.z, 0.0f) * s;
        o[3] = p.y + fmaxf(d.w, 0.0f) * s;
        float lrmin = fminf(d.x, d.z), tbmin = fminf(d.y, d.w);
        float lrmax = fmaxf(d.x, d.z), tbmax = fmaxf(d.y, d.w);
        float cent = sqrtf((lrmin * tbmin) / (lrmax * tbmax));
        if (d.x == -1.0f && d.y == -1.0f && d.z == -1.0f && d.w == -1.0f) cent = -1.0f;
        o[4] = cent;
        return;
    }

    // ---------------- per-class NMS ----------------
    __shared__ float4 sbox[MAXM];      // gathered RAW coords
    __shared__ float  sscore[MAXM];
    __shared__ int    sidx[MAXM];
    __shared__ float4 sbox2[MAXM];     // sorted, OFFSET coords
    __shared__ float  sarea2[MAXM];
    __shared__ int    sidx2[MAXM];
    __shared__ int    ssupp[MAXM];     // fallback only
    __shared__ __align__(16) unsigned int srow[MAXB][8];  // 256-bit rows
    __shared__ int    scnt;
    __shared__ float  swmax[TPB / 32];

    const int c    = blockIdx.x;
    const int lane = tid & 31;
    const int wid  = tid >> 5;
    const float4* b4 = (const float4*)boxes;
    const int4*  cls4 = (const int4*)cls;

    if (tid == 0) scnt = 0;
    __syncthreads();

    float mx = -3.4e38f;

    if (N == 16 * TPB) {
        // ---- fast path: thread owns boxes 4q..4q+3 for q = tid + t*TPB.
        //      ALL global loads (cls, scores, boxes) issue in ONE MLP window;
        //      gather is then fully register-resident (no dependent loads). ----
        int4   cv[4];
        float4 sc4[4];
        float4 vb[16];
        #pragma unroll
        for (int t = 0; t < 4; t++) {
            int q = tid + t * TPB;
            cv[t]  = cls4[q];
            sc4[t] = ((const float4*)scores)[q];
        }
        #pragma unroll
        for (int t = 0; t < 4; t++) {
            int q = tid + t * TPB;
            #pragma unroll
            for (int u = 0; u < 4; u++) vb[t * 4 + u] = b4[4 * q + u];
        }
        #pragma unroll
        for (int k = 0; k < 16; k++)
            mx = fmaxf(mx, fmaxf(fmaxf(vb[k].x, vb[k].y), fmaxf(vb[k].z, vb[k].w)));

        // warp-aggregated slot allocation (1 atomic/warp/group)
        #pragma unroll
        for (int t = 0; t < 4; t++) {
            int q = tid + t * TPB;
            #pragma unroll
            for (int u = 0; u < 4; u++) {
                int ci = (u == 0) ? cv[t].x : (u == 1) ? cv[t].y
                       : (u == 2) ? cv[t].z : cv[t].w;
                bool match = (ci == c);
                unsigned bal = __ballot_sync(0xffffffffu, match);
                if (bal) {                                 // warp-uniform
                    int wbase;
                    if (lane == 0) wbase = atomicAdd(&scnt, __popc(bal));
                    wbase = __shfl_sync(0xffffffffu, wbase, 0);
                    if (match) {
                        int s = wbase + __popc(bal & ((1u << lane) - 1u));
                        int i = 4 * q + u;
                        out[i] = 0.0f;                     // zero keep slot
                        if (s < MAXM) {
                            sbox[s]   = vb[t * 4 + u];
                            sscore[s] = (u == 0) ? sc4[t].x : (u == 1) ? sc4[t].y
                                      : (u == 2) ? sc4[t].z : sc4[t].w;
                            sidx[s]   = i;
                        }
                    }
                }
            }
        }
    } else {
        // ---- generic path (unused for this shape) ----
        for (int i = tid; i < N; i += TPB) {
            float4 v = b4[i];
            mx = fmaxf(mx, fmaxf(fmaxf(v.x, v.y), fmaxf(v.z, v.w)));
        }
        for (int q = tid; q < (N >> 2); q += TPB) {
            int4 cvg = cls4[q];
            int base = q * 4;
            #pragma unroll
            for (int u = 0; u < 4; u++) {
                int ci = (u == 0) ? cvg.x : (u == 1) ? cvg.y : (u == 2) ? cvg.z : cvg.w;
                int i = base + u;
                if (i < N && ci == c) {
                    out[i] = 0.0f;
                    int s = atomicAdd(&scnt, 1);
                    if (s < MAXM) {
                        sbox[s]   = b4[i];
                        sscore[s] = scores[i];
                        sidx[s]   = i;
                    }
                }
            }
        }
    }

    #pragma unroll
    for (int o = 16; o; o >>= 1) mx = fmaxf(mx, __shfl_xor_sync(0xffffffffu, mx, o));
    if (lane == 0) swmax[wid] = mx;
    __syncthreads();                           // covers gather smem + swmax
    mx = swmax[0];
    #pragma unroll
    for (int w = 1; w < TPB / 32; w++) mx = fmaxf(mx, swmax[w]);
    const float off = (float)c * (mx + 1.0f);

    int m = min(scnt, MAXM);
    if (m == 0) return;

    // ---- block-wide stable counting sort by (score desc, idx asc);
    //      offset + area applied in the scatter (matches ref op order) ----
    for (int k = tid; k < m; k += TPB) {
        float sk = sscore[k];
        int   ik = sidx[k];
        int   r  = 0;
        #pragma unroll 4
        for (int j = 0; j < m; j++) {
            float sj = sscore[j];
            r += (sj > sk) || (sj == sk && sidx[j] < ik);
        }
        float4 raw = sbox[k];
        float x1 = raw.x + off, y1 = raw.y + off;
        float x2 = raw.z + off, y2 = raw.w + off;
        sbox2[r]  = make_float4(x1, y1, x2, y2);
        sarea2[r] = (x2 - x1) * (y2 - y1);
        sidx2[r]  = ik;
    }
    __syncthreads();

    if (m <= MAXB) {
        // ---- upper-triangle suppression bitmap, division-free ----
        const int nchunk = (m + 31) >> 5;
        for (int r = wid; r < m; r += TPB / 32) {
            int dch = r >> 5;
            if (lane < dch) srow[r][lane] = 0u;            // dch <= 7
            float4 a  = sbox2[r];
            float  aa = sarea2[r];
            for (int ch = dch; ch < nchunk; ch++) {
                int j = (ch << 5) + lane;
                bool sup = false;
                if (j > r && j < m) {
                    float4 b = sbox2[j];
                    float xi = fminf(a.z, b.z) - fmaxf(a.x, b.x);
                    float yi = fminf(a.w, b.w) - fmaxf(a.y, b.y);
                    float inter = fmaxf(xi, 0.0f) * fmaxf(yi, 0.0f);
                    sup = inter > 0.5f * (aa + sarea2[j] - inter);
                }
                unsigned bm = __ballot_sync(0xffffffffu, sup);
                if (lane == 0) srow[r][ch] = bm;
            }
        }
        __syncthreads();
        if (wid != 0) return;

        // ---- scalar bit-scan, warp 0, software-pipelined row prefetch ----
        typedef unsigned long long u64;
        u64 m0 = 0, m1 = 0, m2 = 0, m3 = 0;
        const u64* rp = (const u64*)srow[0];
        u64 r0 = rp[0], r1 = rp[1], r2 = rp[2], r3 = rp[3];
        for (int i = 0; i < m; i++) {
            u64 n0 = 0, n1 = 0, n2 = 0, n3 = 0;
            if (i + 1 < m) {
                const u64* np = (const u64*)srow[i + 1];
                n0 = np[0]; n1 = np[1]; n2 = np[2]; n3 = np[3];
            }
            int w = i >> 6;
            u64 bit = 1ULL << (i & 63);
            u64 mw = (w == 0) ? m0 : (w == 1) ? m1 : (w == 2) ? m2 : m3;
            if (!(mw & bit)) {
                if (lane == 0) out[sidx2[i]] = 1.0f;
                m0 |= r0; m1 |= r1; m2 |= r2; m3 |= r3;
            }
            r0 = n0; r1 = n1; r2 = n2; r3 = n3;
        }
        return;
    }

    // ---- fallback (m > MAXB, statistically unreachable) ----
    if (wid != 0) return;
    for (int k = lane; k < m; k += 32) ssupp[k] = 0;
    __syncwarp();
    for (int i = 0; i < m; i++) {
        if (ssupp[i]) continue;
        if (lane == 0) out[sidx2[i]] = 1.0f;
        float4 a  = sbox2[i];
        float  aa = sarea2[i];
        for (int j = i + 1 + lane; j < m; j += 32) {
            if (!ssupp[j]) {
                float4 b = sbox2[j];
                float xi = fminf(a.z, b.z) - fmaxf(a.x, b.x);
                float yi = fminf(a.w, b.w) - fmaxf(a.y, b.y);
                float inter = fmaxf(xi, 0.0f) * fmaxf(yi, 0.0f);
                float iou = inter / (aa + sarea2[j] - inter);
                if (iou > 0.5f) ssupp[j] = 1;
            }
        }
        __syncwarp();
    }
}

// ---------------- launch --------------------------------------------------
extern "C" void kernel_launch(void* const* d_in, const int* in_sizes, int n_in,
                              void* d_out, int out_size) {
    const float* boxes   = (const float*)d_in[0];
    const float* scores  = (const float*)d_in[1];
    const int*   cls     = (const int*)d_in[2];
    const float* loc     = (const float*)d_in[3];
    const float* deltas  = (const float*)d_in[4];
    const int*   stridep = (const int*)d_in[5];
    int N = in_sizes[1];        // 4096 boxes
    int L = in_sizes[4] / 4;    // 16384 locations
    float* out = (float*)d_out;

    int pred_blocks = (L + TPB - 1) / TPB;
    k_fused<<<NCLS + pred_blocks, TPB>>>(boxes, scores, cls, loc, deltas,
                                         stridep, out, N, L);
}

// round 14
// speedup vs baseline: 1.2739x; 1.2739x over previous
#include <cuda_runtime.h>
#include <cuda_bf16.h>

#define MAXM   512       // absolute per-class capacity (fallback path)
#define MAXB   256       // fast-path capacity (bitmap rows); actual m ~51
#define NCLS   80
#define TPB    256

typedef unsigned long long u64;

__global__ void __launch_bounds__(TPB) k_fused(const float* __restrict__ boxes,
                                               const float* __restrict__ scores,
                                               const int*   __restrict__ cls,
                                               const float* __restrict__ loc,
                                               const float* __restrict__ deltas,
                                               const int*   __restrict__ stridep,
                                               float* __restrict__ out,
                                               int N, int L) {
    const int tid = threadIdx.x;

    if (blockIdx.x >= NCLS) {
        // ---------------- pred decode + centerness ----------------
        int i = (blockIdx.x - NCLS) * TPB + tid;
        if (i >= L) return;
        float s = (float)stridep[0];
        float4 d = ((const float4*)deltas)[i];
        float2 p = ((const float2*)loc)[i];
        float* o = out + N + 5 * i;
        o[0] = p.x - fmaxf(d.x, 0.0f) * s;
        o[1] = p.y - fmaxf(d.y, 0.0f) * s;
        o[2] = p.x + fmaxf(d.z, 0.0f) * s;
        o[3] = p.y + fmaxf(d.w, 0.0f) * s;
        float lrmin = fminf(d.x, d.z), tbmin = fminf(d.y, d.w);
        float lrmax = fmaxf(d.x, d.z), tbmax = fmaxf(d.y, d.w);
        float cent = sqrtf((lrmin * tbmin) / (lrmax * tbmax));
        if (d.x == -1.0f && d.y == -1.0f && d.z == -1.0f && d.w == -1.0f) cent = -1.0f;
        o[4] = cent;
        return;
    }

    // ---------------- per-class NMS ----------------
    __shared__ float4 sbox[MAXM];      // gathered RAW coords
    __shared__ u64    skey[MAXM];      // (score_bits<<32) | ~idx  (sort key)
    __shared__ float4 sbox2[MAXM];     // sorted, OFFSET coords
    __shared__ float  sarea2[MAXM];
    __shared__ int    sidx2[MAXM];
    __shared__ int    ssupp[MAXM];     // fallback only
    __shared__ __align__(16) unsigned int srow[MAXB][8];  // 256-bit rows
    __shared__ int    swcnt[TPB / 32 + 1];
    __shared__ float  swmax[TPB / 32];
    __shared__ int    scnt;            // generic path only

    const int c    = blockIdx.x;
    const int lane = tid & 31;
    const int wid  = tid >> 5;
    const float4* b4 = (const float4*)boxes;
    const int4*  cls4 = (const int4*)cls;

    float mx = -3.4e38f;
    int m;

    if (N == 16 * TPB) {
        // ---- fast path: thread owns boxes 4q..4q+3 for q = tid + t*TPB.
        //      ALL global loads issue in ONE MLP window; slot allocation by
        //      shuffle prefix-sum (no atomics, no ballots). ----
        int4   cv[4];
        float4 sc4[4];
        float4 vb[16];
        #pragma unroll
        for (int t = 0; t < 4; t++) {
            int q = tid + t * TPB;
            cv[t]  = cls4[q];
            sc4[t] = ((const float4*)scores)[q];
        }
        #pragma unroll
        for (int t = 0; t < 4; t++) {
            int q = tid + t * TPB;
            #pragma unroll
            for (int u = 0; u < 4; u++) vb[t * 4 + u] = b4[4 * q + u];
        }
        #pragma unroll
        for (int k = 0; k < 16; k++)
            mx = fmaxf(mx, fmaxf(fmaxf(vb[k].x, vb[k].y), fmaxf(vb[k].z, vb[k].w)));

        // per-thread match mask over the 16 owned boxes (pure ALU)
        unsigned mmask = 0;
        #pragma unroll
        for (int t = 0; t < 4; t++) {
            if (cv[t].x == c) mmask |= 1u << (t * 4 + 0);
            if (cv[t].y == c) mmask |= 1u << (t * 4 + 1);
            if (cv[t].z == c) mmask |= 1u << (t * 4 + 2);
            if (cv[t].w == c) mmask |= 1u << (t * 4 + 3);
        }
        int cnt = __popc(mmask);

        // warp-exclusive prefix of counts
        int pre = cnt;
        #pragma unroll
        for (int o = 1; o < 32; o <<= 1) {
            int v = __shfl_up_sync(0xffffffffu, pre, o);
            if (lane >= o) pre += v;
        }
        pre -= cnt;                                 // exclusive
        if (lane == 31) swcnt[wid] = pre + cnt;     // warp total

        // warp max for the coordinate reduction
        float wm = mx;
        #pragma unroll
        for (int o = 16; o; o >>= 1) wm = fmaxf(wm, __shfl_xor_sync(0xffffffffu, wm, o));
        if (lane == 0) swmax[wid] = wm;
        __syncthreads();                            // barrier #1

        // block totals (8 smem reads, all threads)
        int base = 0;
        #pragma unroll
        for (int w = 0; w < TPB / 32; w++) {
            int v = swcnt[w];
            if (w < wid) base += v;
        }
        m = 0;
        #pragma unroll
        for (int w = 0; w < TPB / 32; w++) m += swcnt[w];
        mx = swmax[0];
        #pragma unroll
        for (int w = 1; w < TPB / 32; w++) mx = fmaxf(mx, swmax[w]);

        // scatter my matches to contiguous slots [base+pre ...]
        int s = base + pre;
        #pragma unroll
        for (int t = 0; t < 4; t++) {
            #pragma unroll
            for (int u = 0; u < 4; u++) {
                int k = t * 4 + u;
                if (mmask & (1u << k)) {
                    int i = 4 * (tid + t * TPB) + u;
                    out[i] = 0.0f;                  // zero keep slot
                    if (s < MAXM) {
                        sbox[s] = vb[k];
                        float sc = (u == 0) ? sc4[t].x : (u == 1) ? sc4[t].y
                                 : (u == 2) ? sc4[t].z : sc4[t].w;
                        skey[s] = ((u64)__float_as_uint(sc) << 32) | (unsigned)(~i);
                    }
                    s++;
                }
            }
        }
        __syncthreads();                            // barrier #2
    } else {
        // ---- generic path (unused for this shape) ----
        if (tid == 0) scnt = 0;
        __syncthreads();
        for (int i = tid; i < N; i += TPB) {
            float4 v = b4[i];
            mx = fmaxf(mx, fmaxf(fmaxf(v.x, v.y), fmaxf(v.z, v.w)));
        }
        for (int i = tid; i < N; i += TPB) {
            if (cls[i] == c) {
                out[i] = 0.0f;
                int s = atomicAdd(&scnt, 1);
                if (s < MAXM) {
                    sbox[s] = b4[i];
                    skey[s] = ((u64)__float_as_uint(scores[i]) << 32) | (unsigned)(~i);
                }
            }
        }
        #pragma unroll
        for (int o = 16; o; o >>= 1) mx = fmaxf(mx, __shfl_xor_sync(0xffffffffu, mx, o));
        if (lane == 0) swmax[wid] = mx;
        __syncthreads();
        mx = swmax[0];
        #pragma unroll
        for (int w = 1; w < TPB / 32; w++) mx = fmaxf(mx, swmax[w]);
        m = scnt;
    }

    const float off = (float)c * (mx + 1.0f);
    m = min(m, MAXM);
    if (m == 0) return;

    // ---- block-wide stable counting sort on the packed 64-bit key;
    //      (score desc, idx asc): float bits monotone for scores >= 0,
    //      ~idx makes lower index win ties. Offset+area applied in the
    //      scatter (matches ref op order). ----
    for (int k = tid; k < m; k += TPB) {
        u64 kk = skey[k];
        int r = 0;
        #pragma unroll 4
        for (int j = 0; j < m; j++) r += (skey[j] > kk);
        float4 raw = sbox[k];
        float x1 = raw.x + off, y1 = raw.y + off;
        float x2 = raw.z + off, y2 = raw.w + off;
        sbox2[r]  = make_float4(x1, y1, x2, y2);
        sarea2[r] = (x2 - x1) * (y2 - y1);
        sidx2[r]  = ~((unsigned)(kk & 0xffffffffu));
    }
    __syncthreads();                                // barrier #3

    if (m <= MAXB) {
        // ---- upper-triangle suppression bitmap, division-free ----
        const int nchunk = (m + 31) >> 5;
        for (int r = wid; r < m; r += TPB / 32) {
            int dch = r >> 5;
            if (lane < dch) srow[r][lane] = 0u;     // dch <= 7
            float4 a  = sbox2[r];
            float  aa = sarea2[r];
            for (int ch = dch; ch < nchunk; ch++) {
                int j = (ch << 5) + lane;
                bool sup = false;
                if (j > r && j < m) {
                    float4 b = sbox2[j];
                    float xi = fminf(a.z, b.z) - fmaxf(a.x, b.x);
                    float yi = fminf(a.w, b.w) - fmaxf(a.y, b.y);
                    float inter = fmaxf(xi, 0.0f) * fmaxf(yi, 0.0f);
                    sup = inter > 0.5f * (aa + sarea2[j] - inter);
                }
                unsigned bm = __ballot_sync(0xffffffffu, sup);
                if (lane == 0) srow[r][ch] = bm;
            }
        }
        __syncthreads();                            // barrier #4
        if (wid != 0) return;

        // ---- scalar bit-scan, warp 0, software-pipelined row prefetch ----
        u64 m0 = 0, m1 = 0, m2 = 0, m3 = 0;
        const u64* rp = (const u64*)srow[0];
        u64 r0 = rp[0], r1 = rp[1], r2 = rp[2], r3 = rp[3];
        for (int i = 0; i < m; i++) {
            u64 n0 = 0, n1 = 0, n2 = 0, n3 = 0;
            if (i + 1 < m) {
                const u64* np = (const u64*)srow[i + 1];
                n0 = np[0]; n1 = np[1]; n2 = np[2]; n3 = np[3];
            }
            int w = i >> 6;
            u64 bit = 1ULL << (i & 63);
            u64 mw = (w == 0) ? m0 : (w == 1) ? m1 : (w == 2) ? m2 : m3;
            if (!(mw & bit)) {
                if (lane == 0) out[sidx2[i]] = 1.0f;
                m0 |= r0; m1 |= r1; m2 |= r2; m3 |= r3;
            }
            r0 = n0; r1 = n1; r2 = n2; r3 = n3;
        }
        return;
    }

    // ---- fallback (m > MAXB, statistically unreachable) ----
    if (wid != 0) return;
    for (int k = lane; k < m; k += 32) ssupp[k] = 0;
    __syncwarp();
    for (int i = 0; i < m; i++) {
        if (ssupp[i]) continue;
        if (lane == 0) out[sidx2[i]] = 1.0f;
        float4 a  = sbox2[i];
        float  aa = sarea2[i];
        for (int j = i + 1 + lane; j < m; j += 32) {
            if (!ssupp[j]) {
                float4 b = sbox2[j];
                float xi = fminf(a.z, b.z) - fmaxf(a.x, b.x);
                float yi = fminf(a.w, b.w) - fmaxf(a.y, b.y);
                float inter = fmaxf(xi, 0.0f) * fmaxf(yi, 0.0f);
                float iou = inter / (aa + sarea2[j] - inter);
                if (iou > 0.5f) ssupp[j] = 1;
            }
        }
        __syncwarp();
    }
}

// ---------------- launch --------------------------------------------------
extern "C" void kernel_launch(void* const* d_in, const int* in_sizes, int n_in,
                              void* d_out, int out_size) {
    const float* boxes   = (const float*)d_in[0];
    const float* scores  = (const float*)d_in[1];
    const int*   cls     = (const int*)d_in[2];
    const float* loc     = (const float*)d_in[3];
    const float* deltas  = (const float*)d_in[4];
    const int*   stridep = (const int*)d_in[5];
    int N = in_sizes[1];        // 4096 boxes
    int L = in_sizes[4] / 4;    // 16384 locations
    float* out = (float*)d_out;

    int pred_blocks = (L + TPB - 1) / TPB;
    k_fused<<<NCLS + pred_blocks, TPB>>>(boxes, scores, cls, loc, deltas,
                                         stridep, out, N, L);
}

// round 15
// speedup vs baseline: 1.2931x; 1.0151x over previous
#include <cuda_runtime.h>
#include <cuda_bf16.h>

#define MAXM   512       // absolute per-class capacity (fallback path)
#define MAXB   256       // fast-path capacity (bitmap rows); actual m ~51
#define NCLS   80
#define TPB    256

typedef unsigned long long u64;

__global__ void __launch_bounds__(TPB) k_fused(const float* __restrict__ boxes,
                                               const float* __restrict__ scores,
                                               const int*   __restrict__ cls,
                                               const float* __restrict__ loc,
                                               const float* __restrict__ deltas,
                                               const int*   __restrict__ stridep,
                                               float* __restrict__ out,
                                               int N, int L) {
    const int tid = threadIdx.x;

    if (blockIdx.x >= NCLS) {
        // ---------------- pred decode + centerness ----------------
        int i = (blockIdx.x - NCLS) * TPB + tid;
        if (i >= L) return;
        float s = (float)stridep[0];
        float4 d = ((const float4*)deltas)[i];
        float2 p = ((const float2*)loc)[i];
        float* o = out + N + 5 * i;
        o[0] = p.x - fmaxf(d.x, 0.0f) * s;
        o[1] = p.y - fmaxf(d.y, 0.0f) * s;
        o[2] = p.x + fmaxf(d.z, 0.0f) * s;
        o[3] = p.y + fmaxf(d.w, 0.0f) * s;
        float lrmin = fminf(d.x, d.z), tbmin = fminf(d.y, d.w);
        float lrmax = fmaxf(d.x, d.z), tbmax = fmaxf(d.y, d.w);
        float cent = sqrtf((lrmin * tbmin) / (lrmax * tbmax));
        if (d.x == -1.0f && d.y == -1.0f && d.z == -1.0f && d.w == -1.0f) cent = -1.0f;
        o[4] = cent;
        return;
    }

    // ---------------- per-class NMS ----------------
    __shared__ float4 sbox[MAXM];      // gathered RAW coords
    __shared__ u64    skey[MAXM];      // (score_bits<<32) | ~idx  (sort key)
    __shared__ float4 sbox2[MAXM];     // sorted, OFFSET coords
    __shared__ float  sarea2[MAXM];
    __shared__ int    sidx2[MAXM];
    __shared__ int    ssupp[MAXM];     // fallback only
    __shared__ __align__(16) unsigned int srow[MAXB][8];  // 256-bit rows
    __shared__ int    swcnt[TPB / 32 + 1];
    __shared__ float  swmax[TPB / 32];
    __shared__ int    scnt;            // generic path only

    const int c    = blockIdx.x;
    const int lane = tid & 31;
    const int wid  = tid >> 5;
    const float4* b4 = (const float4*)boxes;
    const int4*  cls4 = (const int4*)cls;

    float mx = -3.4e38f;
    int m;

    if (N == 16 * TPB) {
        // ---- fast path: thread owns boxes 4q..4q+3 for q = tid + t*TPB.
        //      ALL global loads issue in ONE MLP window; slot allocation by
        //      shuffle prefix-sum (no atomics, no ballots). ----
        int4   cv[4];
        float4 sc4[4];
        float4 vb[16];
        #pragma unroll
        for (int t = 0; t < 4; t++) {
            int q = tid + t * TPB;
            cv[t]  = cls4[q];
            sc4[t] = ((const float4*)scores)[q];
        }
        #pragma unroll
        for (int t = 0; t < 4; t++) {
            int q = tid + t * TPB;
            #pragma unroll
            for (int u = 0; u < 4; u++) vb[t * 4 + u] = b4[4 * q + u];
        }
        #pragma unroll
        for (int k = 0; k < 16; k++)
            mx = fmaxf(mx, fmaxf(fmaxf(vb[k].x, vb[k].y), fmaxf(vb[k].z, vb[k].w)));

        // per-thread match mask over the 16 owned boxes (pure ALU);
        // zero keep slots immediately (independent of slot computation)
        unsigned mmask = 0;
        #pragma unroll
        for (int t = 0; t < 4; t++) {
            #pragma unroll
            for (int u = 0; u < 4; u++) {
                int ci = (u == 0) ? cv[t].x : (u == 1) ? cv[t].y
                       : (u == 2) ? cv[t].z : cv[t].w;
                if (ci == c) {
                    mmask |= 1u << (t * 4 + u);
                    out[4 * (tid + t * TPB) + u] = 0.0f;
                }
            }
        }
        int cnt = __popc(mmask);

        // warp-exclusive prefix of counts
        int pre = cnt;
        #pragma unroll
        for (int o = 1; o < 32; o <<= 1) {
            int v = __shfl_up_sync(0xffffffffu, pre, o);
            if (lane >= o) pre += v;
        }
        pre -= cnt;                                 // exclusive
        if (lane == 31) swcnt[wid] = pre + cnt;     // warp total

        // warp max for the coordinate reduction
        float wm = mx;
        #pragma unroll
        for (int o = 16; o; o >>= 1) wm = fmaxf(wm, __shfl_xor_sync(0xffffffffu, wm, o));
        if (lane == 0) swmax[wid] = wm;
        __syncthreads();                            // barrier #1

        int base = 0;
        #pragma unroll
        for (int w = 0; w < TPB / 32; w++) {
            int v = swcnt[w];
            if (w < wid) base += v;
        }
        m = 0;
        #pragma unroll
        for (int w = 0; w < TPB / 32; w++) m += swcnt[w];
        mx = swmax[0];
        #pragma unroll
        for (int w = 1; w < TPB / 32; w++) mx = fmaxf(mx, swmax[w]);

        // scatter my matches to contiguous slots [base+pre ...]
        int s = base + pre;
        #pragma unroll
        for (int t = 0; t < 4; t++) {
            #pragma unroll
            for (int u = 0; u < 4; u++) {
                int k = t * 4 + u;
                if (mmask & (1u << k)) {
                    int i = 4 * (tid + t * TPB) + u;
                    if (s < MAXM) {
                        sbox[s] = vb[k];
                        float sc = (u == 0) ? sc4[t].x : (u == 1) ? sc4[t].y
                                 : (u == 2) ? sc4[t].z : sc4[t].w;
                        skey[s] = ((u64)__float_as_uint(sc) << 32) | (unsigned)(~i);
                    }
                    s++;
                }
            }
        }
        __syncthreads();                            // barrier #2
    } else {
        // ---- generic path (unused for this shape) ----
        if (tid == 0) scnt = 0;
        __syncthreads();
        for (int i = tid; i < N; i += TPB) {
            float4 v = b4[i];
            mx = fmaxf(mx, fmaxf(fmaxf(v.x, v.y), fmaxf(v.z, v.w)));
        }
        for (int i = tid; i < N; i += TPB) {
            if (cls[i] == c) {
                out[i] = 0.0f;
                int s = atomicAdd(&scnt, 1);
                if (s < MAXM) {
                    sbox[s] = b4[i];
                    skey[s] = ((u64)__float_as_uint(scores[i]) << 32) | (unsigned)(~i);
                }
            }
        }
        #pragma unroll
        for (int o = 16; o; o >>= 1) mx = fmaxf(mx, __shfl_xor_sync(0xffffffffu, mx, o));
        if (lane == 0) swmax[wid] = mx;
        __syncthreads();
        mx = swmax[0];
        #pragma unroll
        for (int w = 1; w < TPB / 32; w++) mx = fmaxf(mx, swmax[w]);
        m = scnt;
    }

    const float off = (float)c * (mx + 1.0f);
    m = min(m, MAXM);
    if (m == 0) return;

    // ---- block-wide stable counting sort on the packed 64-bit key ----
    for (int k = tid; k < m; k += TPB) {
        u64 kk = skey[k];
        int r = 0;
        #pragma unroll 4
        for (int j = 0; j < m; j++) r += (skey[j] > kk);
        float4 raw = sbox[k];
        float x1 = raw.x + off, y1 = raw.y + off;
        float x2 = raw.z + off, y2 = raw.w + off;
        sbox2[r]  = make_float4(x1, y1, x2, y2);
        sarea2[r] = (x2 - x1) * (y2 - y1);
        sidx2[r]  = ~((unsigned)(kk & 0xffffffffu));
    }
    __syncthreads();                                // barrier #3

    if (m <= MAXB) {
        // ---- upper-triangle suppression bitmap, division-free ----
        const int nchunk = (m + 31) >> 5;
        for (int r = wid; r < m; r += TPB / 32) {
            int dch = r >> 5;
            if (lane < dch) srow[r][lane] = 0u;     // dch <= 7
            float4 a  = sbox2[r];
            float  aa = sarea2[r];
            for (int ch = dch; ch < nchunk; ch++) {
                int j = (ch << 5) + lane;
                bool sup = false;
                if (j > r && j < m) {
                    float4 b = sbox2[j];
                    float xi = fminf(a.z, b.z) - fmaxf(a.x, b.x);
                    float yi = fminf(a.w, b.w) - fmaxf(a.y, b.y);
                    float inter = fmaxf(xi, 0.0f) * fmaxf(yi, 0.0f);
                    sup = inter > 0.5f * (aa + sarea2[j] - inter);
                }
                unsigned bm = __ballot_sync(0xffffffffu, sup);
                if (lane == 0) srow[r][ch] = bm;
            }
        }
        __syncthreads();                            // barrier #4
        if (wid != 0) return;

        // ---- branchless scalar bit-scan, warp 0: no branch, no STG in the
        //      chain; keep decisions accumulate into registers. Depth-2 row
        //      prefetch covers the 29-cyc LDS. ----
        u64 m0 = 0, m1 = 0, m2 = 0, m3 = 0;
        u64 k0 = 0, k1 = 0, k2 = 0, k3 = 0;        // keep masks
        const u64* rp0 = (const u64*)srow[0];
        u64 a0 = rp0[0], a1 = rp0[1], a2 = rp0[2], a3 = rp0[3];   // row i
        u64 b0 = 0, b1 = 0, b2 = 0, b3 = 0;                       // row i+1
        if (m > 1) {
            const u64* rp1 = (const u64*)srow[1];
            b0 = rp1[0]; b1 = rp1[1]; b2 = rp1[2]; b3 = rp1[3];
        }
        for (int i = 0; i < m; i++) {
            u64 c0 = 0, c1 = 0, c2 = 0, c3 = 0;                   // row i+2
            if (i + 2 < m) {
                const u64* rp2 = (const u64*)srow[i + 2];
                c0 = rp2[0]; c1 = rp2[1]; c2 = rp2[2]; c3 = rp2[3];
            }
            int w = i >> 6;
            int bit = i & 63;
            u64 mw = (w == 0) ? m0 : (w == 1) ? m1 : (w == 2) ? m2 : m3;
            u64 kp = ((mw >> bit) & 1ULL) ^ 1ULL;                 // 1 if keep
            u64 sel = (u64)0 - kp;                                // all-ones if keep
            u64 kb = kp << bit;
            if (w == 0) k0 |= kb; else if (w == 1) k1 |= kb;
            else if (w == 2) k2 |= kb; else k3 |= kb;
            m0 |= a0 & sel; m1 |= a1 & sel; m2 |= a2 & sel; m3 |= a3 & sel;
            a0 = b0; a1 = b1; a2 = b2; a3 = b3;
            b0 = c0; b1 = c1; b2 = c2; b3 = c3;
        }
        // parallel deferred keep-store (all lanes hold identical keep masks)
        for (int i = lane; i < m; i += 32) {
            u64 kw = (i < 64) ? k0 : (i < 128) ? k1 : (i < 192) ? k2 : k3;
            if ((kw >> (i & 63)) & 1ULL) out[sidx2[i]] = 1.0f;
        }
        return;
    }

    // ---- fallback (m > MAXB, statistically unreachable) ----
    if (wid != 0) return;
    for (int k = lane; k < m; k += 32) ssupp[k] = 0;
    __syncwarp();
    for (int i = 0; i < m; i++) {
        if (ssupp[i]) continue;
        if (lane == 0) out[sidx2[i]] = 1.0f;
        float4 a  = sbox2[i];
        float  aa = sarea2[i];
        for (int j = i + 1 + lane; j < m; j += 32) {
            if (!ssupp[j]) {
                float4 b = sbox2[j];
                float xi = fminf(a.z, b.z) - fmaxf(a.x, b.x);
                float yi = fminf(a.w, b.w) - fmaxf(a.y, b.y);
                float inter = fmaxf(xi, 0.0f) * fmaxf(yi, 0.0f);
                float iou = inter / (aa + sarea2[j] - inter);
                if (iou > 0.5f) ssupp[j] = 1;
            }
        }
        __syncwarp();
    }
}

// ---------------- launch --------------------------------------------------
extern "C" void kernel_launch(void* const* d_in, const int* in_sizes, int n_in,
                              void* d_out, int out_size) {
    const float* boxes   = (const float*)d_in[0];
    const float* scores  = (const float*)d_in[1];
    const int*   cls     = (const int*)d_in[2];
    const float* loc     = (const float*)d_in[3];
    const float* deltas  = (const float*)d_in[4];
    const int*   stridep = (const int*)d_in[5];
    int N = in_sizes[1];        // 4096 boxes
    int L = in_sizes[4] / 4;    // 16384 locations
    float* out = (float*)d_out;

    int pred_blocks = (L + TPB - 1) / TPB;
    k_fused<<<NCLS + pred_blocks, TPB>>>(boxes, scores, cls, loc, deltas,
                                         stridep, out, N, L);
}